// round 1
// baseline (speedup 1.0000x reference)
#include <cuda_runtime.h>

#define Bn 32
#define Tn 2048
#define Fn 2048
#define DQn 1024
#define UNITSn 1024
#define HALFn 1024      // F/2
#define CONCATn 2048    // HALF + DQ
#define TSEG 16

// Scratch (allocation-free rule: __device__ globals)
__device__ float g_w[CONCATn];          // W1 @ V
__device__ float g_qb[Bn];              // query[b]·w[1024:] + b1·V + bV
__device__ float g_score[Bn * Tn];      // raw scores
__device__ float g_partial[Bn * TSEG * Fn];  // 4 MB context partials

// ---------------------------------------------------------------------------
// K1: w[c] = sum_u W1[c,u] * V[u]   (one warp per output c)
// ---------------------------------------------------------------------------
__global__ void k_w(const float* __restrict__ W1, const float* __restrict__ V) {
    int warp = (blockIdx.x * blockDim.x + threadIdx.x) >> 5;
    int lane = threadIdx.x & 31;
    if (warp >= CONCATn) return;
    const float4* row = reinterpret_cast<const float4*>(W1 + (size_t)warp * UNITSn);
    const float4* v4  = reinterpret_cast<const float4*>(V);
    float acc = 0.f;
#pragma unroll
    for (int i = 0; i < UNITSn / 128; i++) {
        float4 a = row[lane + i * 32];
        float4 b = v4[lane + i * 32];
        acc += a.x * b.x + a.y * b.y + a.z * b.z + a.w * b.w;
    }
#pragma unroll
    for (int o = 16; o; o >>= 1) acc += __shfl_xor_sync(0xffffffffu, acc, o);
    if (lane == 0) g_w[warp] = acc;
}

// ---------------------------------------------------------------------------
// K2: qb[b] = query[b]·w[HALF:] + b1·V + bV   (one warp per batch, 1 block)
// ---------------------------------------------------------------------------
__global__ void k_qb(const float* __restrict__ query, const float* __restrict__ b1,
                     const float* __restrict__ V, const float* __restrict__ bV) {
    int b = threadIdx.x >> 5;
    int lane = threadIdx.x & 31;
    const float4* q4 = reinterpret_cast<const float4*>(query + (size_t)b * DQn);
    const float4* w4 = reinterpret_cast<const float4*>(g_w + HALFn);
    const float4* b4 = reinterpret_cast<const float4*>(b1);
    const float4* v4 = reinterpret_cast<const float4*>(V);
    float acc = 0.f;
#pragma unroll
    for (int i = 0; i < DQn / 128; i++) {
        float4 q = q4[lane + i * 32];
        float4 w = w4[lane + i * 32];
        acc += q.x * w.x + q.y * w.y + q.z * w.z + q.w * w.w;
        float4 bb = b4[lane + i * 32];
        float4 vv = v4[lane + i * 32];
        acc += bb.x * vv.x + bb.y * vv.y + bb.z * vv.z + bb.w * vv.w;
    }
#pragma unroll
    for (int o = 16; o; o >>= 1) acc += __shfl_xor_sync(0xffffffffu, acc, o);
    if (lane == 0) g_qb[b] = acc + bV[0];
}

// ---------------------------------------------------------------------------
// K3: score[b,t] = values[b,t,:1024]·w[:1024] + qb[b]
//     one warp per (b,t) row; w cached in smem; 256 MB streaming read
// ---------------------------------------------------------------------------
__global__ void k_score(const float* __restrict__ values) {
    __shared__ float sw[HALFn];
    for (int i = threadIdx.x; i < HALFn; i += 256) sw[i] = g_w[i];
    __syncthreads();
    int warp = threadIdx.x >> 5;
    int lane = threadIdx.x & 31;
    int row = blockIdx.x * 8 + warp;          // row in [0, B*T)
    const float4* v4 = reinterpret_cast<const float4*>(values + (size_t)row * Fn);
    const float4* w4 = reinterpret_cast<const float4*>(sw);
    float acc = 0.f;
#pragma unroll
    for (int i = 0; i < HALFn / 128; i++) {
        float4 v = v4[lane + i * 32];
        float4 w = w4[lane + i * 32];
        acc += v.x * w.x + v.y * w.y + v.z * w.z + v.w * w.w;
    }
#pragma unroll
    for (int o = 16; o; o >>= 1) acc += __shfl_xor_sync(0xffffffffu, acc, o);
    if (lane == 0) g_score[row] = acc + g_qb[row >> 11];   // row / T
}

// ---------------------------------------------------------------------------
// K4: softmax over T per batch; writes attention weights into d_out tail
// ---------------------------------------------------------------------------
__global__ void k_softmax(float* __restrict__ aw) {
    int b = blockIdx.x;
    int lane = threadIdx.x & 31;
    int warp = threadIdx.x >> 5;   // 32 warps
    __shared__ float red[32];
    __shared__ float s_bcast;

    float s0 = g_score[b * Tn + threadIdx.x];
    float s1 = g_score[b * Tn + threadIdx.x + 1024];

    // ---- max reduce ----
    float m = fmaxf(s0, s1);
#pragma unroll
    for (int o = 16; o; o >>= 1) m = fmaxf(m, __shfl_xor_sync(0xffffffffu, m, o));
    if (lane == 0) red[warp] = m;
    __syncthreads();
    if (warp == 0) {
        float v = red[lane];
#pragma unroll
        for (int o = 16; o; o >>= 1) v = fmaxf(v, __shfl_xor_sync(0xffffffffu, v, o));
        if (lane == 0) s_bcast = v;
    }
    __syncthreads();
    m = s_bcast;

    // ---- sum reduce ----
    float e0 = __expf(s0 - m);
    float e1 = __expf(s1 - m);
    float s = e0 + e1;
#pragma unroll
    for (int o = 16; o; o >>= 1) s += __shfl_xor_sync(0xffffffffu, s, o);
    __syncthreads();
    if (lane == 0) red[warp] = s;
    __syncthreads();
    if (warp == 0) {
        float v = red[lane];
#pragma unroll
        for (int o = 16; o; o >>= 1) v += __shfl_xor_sync(0xffffffffu, v, o);
        if (lane == 0) s_bcast = v;
    }
    __syncthreads();
    float inv = 1.0f / s_bcast;

    aw[b * Tn + threadIdx.x]        = e0 * inv;
    aw[b * Tn + threadIdx.x + 1024] = e1 * inv;
}

// ---------------------------------------------------------------------------
// K5: context partials: partial[b,seg,f] = sum_{t in seg} aw[b,t]*values[b,t,f]
//     grid (TSEG, B), 512 threads × float4 covers F=2048; 512 MB streaming read
// ---------------------------------------------------------------------------
__global__ void k_ctx(const float* __restrict__ values, const float* __restrict__ aw) {
    int seg = blockIdx.x;
    int b   = blockIdx.y;
    const int TS = Tn / TSEG;   // 128
    __shared__ float sa[TS];
    int tbase = seg * TS;
    if (threadIdx.x < TS) sa[threadIdx.x] = aw[b * Tn + tbase + threadIdx.x];
    __syncthreads();

    const float4* vp = reinterpret_cast<const float4*>(
        values + ((size_t)(b * Tn + tbase)) * Fn) + threadIdx.x;
    float4 acc = make_float4(0.f, 0.f, 0.f, 0.f);
#pragma unroll 4
    for (int t = 0; t < TS; t++) {
        float a = sa[t];
        float4 v = vp[(size_t)t * (Fn / 4)];
        acc.x += a * v.x;
        acc.y += a * v.y;
        acc.z += a * v.z;
        acc.w += a * v.w;
    }
    reinterpret_cast<float4*>(g_partial + ((size_t)(b * TSEG + seg)) * Fn)[threadIdx.x] = acc;
}

// ---------------------------------------------------------------------------
// K6: reduce TSEG partials -> context[b,f]
// ---------------------------------------------------------------------------
__global__ void k_reduce(float* __restrict__ ctx) {
    int idx = blockIdx.x * 256 + threadIdx.x;   // [0, B*F)
    int b = idx >> 11;                           // / F
    int f = idx & (Fn - 1);
    float acc = 0.f;
#pragma unroll
    for (int s = 0; s < TSEG; s++)
        acc += g_partial[((size_t)(b * TSEG + s)) * Fn + f];
    ctx[idx] = acc;
}

// ---------------------------------------------------------------------------
extern "C" void kernel_launch(void* const* d_in, const int* in_sizes, int n_in,
                              void* d_out, int out_size) {
    const float* query  = (const float*)d_in[0];
    const float* values = (const float*)d_in[1];
    const float* W1     = (const float*)d_in[2];
    const float* b1     = (const float*)d_in[3];
    const float* V      = (const float*)d_in[4];
    const float* bV     = (const float*)d_in[5];

    float* out = (float*)d_out;
    float* ctx = out;                 // [B, F]   context_vector (32,1,2048)
    float* aw  = out + Bn * Fn;       // [B, T]   attention_weights (32,2048,1)

    k_w<<<CONCATn / 8, 256>>>(W1, V);
    k_qb<<<1, 1024>>>(query, b1, V, bV);
    k_score<<<(Bn * Tn) / 8, 256>>>(values);
    k_softmax<<<Bn, 1024>>>(aw);
    dim3 gctx(TSEG, Bn);
    k_ctx<<<gctx, 512>>>(values, aw);
    k_reduce<<<(Bn * Fn) / 256, 256>>>(ctx);
}

// round 2
// speedup vs baseline: 1.0821x; 1.0821x over previous
#include <cuda_runtime.h>

#define Bn 32
#define Tn 2048
#define Fn 2048
#define DQn 1024
#define UNITSn 1024
#define HALFn 1024      // F/2
#define CONCATn 2048    // HALF + DQ
#define SEG 16          // T segments per batch
#define TS (Tn / SEG)   // 128 rows per block
#define TILE 16         // rows per inner tile (= warps per block /? block has 16 warps)

// Scratch (allocation-free rule: __device__ globals)
__device__ float g_w[CONCATn];              // W1 @ V
__device__ float g_qb[Bn];                  // query[b]·w[1024:] + b1·V + bV
__device__ float g_score[Bn * Tn];          // raw scores
__device__ float g_partial[Bn * SEG * Fn];  // 4 MB context partials (unnormalized)
__device__ float g_m[Bn * SEG];             // per-segment running max
__device__ float g_Z[Bn * SEG];             // per-segment exp-sum (at local max)
__device__ float g_gm[Bn];                  // global max per batch
__device__ float g_invZ[Bn];                // 1/Z per batch

// ---------------------------------------------------------------------------
// K1: w[c] = sum_u W1[c,u] * V[u]   (one warp per output c)
// ---------------------------------------------------------------------------
__global__ void k_w(const float* __restrict__ W1, const float* __restrict__ V) {
    int warp = (blockIdx.x * blockDim.x + threadIdx.x) >> 5;
    int lane = threadIdx.x & 31;
    if (warp >= CONCATn) return;
    const float4* row = reinterpret_cast<const float4*>(W1 + (size_t)warp * UNITSn);
    const float4* v4  = reinterpret_cast<const float4*>(V);
    float acc = 0.f;
#pragma unroll
    for (int i = 0; i < UNITSn / 128; i++) {
        float4 a = row[lane + i * 32];
        float4 b = v4[lane + i * 32];
        acc += a.x * b.x + a.y * b.y + a.z * b.z + a.w * b.w;
    }
#pragma unroll
    for (int o = 16; o; o >>= 1) acc += __shfl_xor_sync(0xffffffffu, acc, o);
    if (lane == 0) g_w[warp] = acc;
}

// ---------------------------------------------------------------------------
// K2: qb[b] = query[b]·w[HALF:] + b1·V + bV   (one warp per batch, 1 block)
// ---------------------------------------------------------------------------
__global__ void k_qb(const float* __restrict__ query, const float* __restrict__ b1,
                     const float* __restrict__ V, const float* __restrict__ bV) {
    int b = threadIdx.x >> 5;
    int lane = threadIdx.x & 31;
    const float4* q4 = reinterpret_cast<const float4*>(query + (size_t)b * DQn);
    const float4* w4 = reinterpret_cast<const float4*>(g_w + HALFn);
    const float4* b4 = reinterpret_cast<const float4*>(b1);
    const float4* v4 = reinterpret_cast<const float4*>(V);
    float acc = 0.f;
#pragma unroll
    for (int i = 0; i < DQn / 128; i++) {
        float4 q = q4[lane + i * 32];
        float4 w = w4[lane + i * 32];
        acc += q.x * w.x + q.y * w.y + q.z * w.z + q.w * w.w;
        float4 bb = b4[lane + i * 32];
        float4 vv = v4[lane + i * 32];
        acc += bb.x * vv.x + bb.y * vv.y + bb.z * vv.z + bb.w * vv.w;
    }
#pragma unroll
    for (int o = 16; o; o >>= 1) acc += __shfl_xor_sync(0xffffffffu, acc, o);
    if (lane == 0) g_qb[b] = acc + bV[0];
}

// ---------------------------------------------------------------------------
// K3 (fused): per (seg, b) block — online-softmax context over TS rows.
//   Tile of 16 rows:
//     phase A: warp w computes s = values[row_w,:1024]·w + qb  (reads 4KB/row)
//     phase B: every thread FMAs its float4 column of all 16 full rows into acc,
//              weighted by e^{s - m_run}. Phase-A bytes re-hit in L1/L2.
//   Single DRAM read of values (512 MB total).
// ---------------------------------------------------------------------------
__global__ __launch_bounds__(512) void k_fused(const float* __restrict__ values) {
    __shared__ float sw[HALFn];    // 4 KB
    __shared__ float s_s[TILE];
    __shared__ float s_e[TILE];

    int seg = blockIdx.x, b = blockIdx.y;
    int tid = threadIdx.x, warp = tid >> 5, lane = tid & 31;

    for (int i = tid; i < HALFn; i += 512) sw[i] = g_w[i];
    float qb = g_qb[b];
    __syncthreads();

    int tbase = seg * TS;
    const float* base = values + ((size_t)(b * Tn + tbase)) * Fn;
    const float4* w4 = reinterpret_cast<const float4*>(sw);

    float4 acc = make_float4(0.f, 0.f, 0.f, 0.f);
    float m_run = -1e30f;
    float Z = 0.f;

#pragma unroll 1
    for (int tile = 0; tile < TS / TILE; tile++) {
        // ---- phase A: scores (warp per row) ----
        const float4* row4 = reinterpret_cast<const float4*>(
            base + (size_t)(tile * TILE + warp) * Fn);
        float d = 0.f;
#pragma unroll
        for (int i = 0; i < HALFn / 128; i++) {
            float4 v = row4[lane + i * 32];
            float4 w = w4[lane + i * 32];
            d += v.x * w.x + v.y * w.y + v.z * w.z + v.w * w.w;
        }
#pragma unroll
        for (int o = 16; o; o >>= 1) d += __shfl_xor_sync(0xffffffffu, d, o);
        if (lane == 0) {
            float s = d + qb;
            s_s[warp] = s;
            g_score[b * Tn + tbase + tile * TILE + warp] = s;
        }
        __syncthreads();

        // ---- online softmax bookkeeping ----
        float tm = s_s[0];
#pragma unroll
        for (int i = 1; i < TILE; i++) tm = fmaxf(tm, s_s[i]);
        float new_m = fmaxf(m_run, tm);
        if (lane == 0) s_e[warp] = __expf(s_s[warp] - new_m);
        float corr = __expf(m_run - new_m);
        m_run = new_m;
        __syncthreads();

        float esum = 0.f;
        float e[TILE];
#pragma unroll
        for (int i = 0; i < TILE; i++) { e[i] = s_e[i]; esum += e[i]; }
        Z = Z * corr + esum;
        acc.x *= corr; acc.y *= corr; acc.z *= corr; acc.w *= corr;

        // ---- phase B: weighted accumulate (thread per float4 column) ----
        const float4* vp = reinterpret_cast<const float4*>(base)
                         + (size_t)(tile * TILE) * (Fn / 4) + tid;
#pragma unroll
        for (int t = 0; t < TILE; t++) {
            float4 v = vp[(size_t)t * (Fn / 4)];
            acc.x += e[t] * v.x;
            acc.y += e[t] * v.y;
            acc.z += e[t] * v.z;
            acc.w += e[t] * v.w;
        }
        __syncthreads();   // protect s_s/s_e for next tile
    }

    reinterpret_cast<float4*>(g_partial + ((size_t)(b * SEG + seg)) * Fn)[tid] = acc;
    if (tid == 0) {
        g_m[b * SEG + seg] = m_run;
        g_Z[b * SEG + seg] = Z;
    }
}

// ---------------------------------------------------------------------------
// K4: combine segment partials -> context[b,f]; store (gm, 1/Z) per batch
// ---------------------------------------------------------------------------
__global__ void k_combine(float* __restrict__ ctx) {
    int b = blockIdx.x;
    int tid = threadIdx.x;   // 512
    __shared__ float sm[SEG], sz[SEG];
    if (tid < SEG) { sm[tid] = g_m[b * SEG + tid]; sz[tid] = g_Z[b * SEG + tid]; }
    __syncthreads();

    float gm = sm[0];
#pragma unroll
    for (int i = 1; i < SEG; i++) gm = fmaxf(gm, sm[i]);
    float Zg = 0.f;
    float sc[SEG];
#pragma unroll
    for (int i = 0; i < SEG; i++) { sc[i] = __expf(sm[i] - gm); Zg += sz[i] * sc[i]; }
    float inv = 1.0f / Zg;

    float4 a = make_float4(0.f, 0.f, 0.f, 0.f);
#pragma unroll
    for (int s = 0; s < SEG; s++) {
        float w = sc[s] * inv;
        float4 c = reinterpret_cast<const float4*>(
            g_partial + ((size_t)(b * SEG + s)) * Fn)[tid];
        a.x += w * c.x; a.y += w * c.y; a.z += w * c.z; a.w += w * c.w;
    }
    reinterpret_cast<float4*>(ctx + (size_t)b * Fn)[tid] = a;

    if (tid == 0) { g_gm[b] = gm; g_invZ[b] = inv; }
}

// ---------------------------------------------------------------------------
// K5: normalized attention weights from raw scores
// ---------------------------------------------------------------------------
__global__ void k_aw(float* __restrict__ aw) {
    int idx = blockIdx.x * 1024 + threadIdx.x;   // [0, B*T)
    int b = idx >> 11;
    aw[idx] = __expf(g_score[idx] - g_gm[b]) * g_invZ[b];
}

// ---------------------------------------------------------------------------
extern "C" void kernel_launch(void* const* d_in, const int* in_sizes, int n_in,
                              void* d_out, int out_size) {
    const float* query  = (const float*)d_in[0];
    const float* values = (const float*)d_in[1];
    const float* W1     = (const float*)d_in[2];
    const float* b1     = (const float*)d_in[3];
    const float* V      = (const float*)d_in[4];
    const float* bV     = (const float*)d_in[5];

    float* out = (float*)d_out;
    float* ctx = out;                 // [B, F]   context_vector (32,1,2048)
    float* aw  = out + Bn * Fn;       // [B, T]   attention_weights (32,2048,1)

    k_w<<<CONCATn / 8, 256>>>(W1, V);
    k_qb<<<1, 1024>>>(query, b1, V, bV);
    dim3 gf(SEG, Bn);
    k_fused<<<gf, 512>>>(values);
    k_combine<<<Bn, 512>>>(ctx);
    k_aw<<<(Bn * Tn) / 1024, 1024>>>(aw);
}

// round 3
// speedup vs baseline: 1.1585x; 1.0707x over previous
#include <cuda_runtime.h>

#define Bn 32
#define Tn 2048
#define Fn 2048
#define DQn 1024
#define UNITSn 1024
#define HALFn 1024      // F/2
#define CONCATn 2048    // HALF + DQ
#define SEG 16          // T segments per batch
#define TS (Tn / SEG)   // 128 rows per segment block
#define TILE 16         // rows per inner tile in kS (warp per row)

// Scratch (allocation-free rule: __device__ globals)
__device__ float g_w[CONCATn];                 // W1 @ V
__device__ float g_qb[Bn];                     // query[b]·w[1024:] + b1·V + bV
__device__ float g_score[Bn * Tn];             // raw scores
__device__ float g_partialA[Bn * SEG * HALFn]; // first-half ctx partials (per-seg max scale)
__device__ float g_partialB[Bn * SEG * HALFn]; // second-half ctx partials (final aw scale)
__device__ float g_m[Bn * SEG];                // per-segment running max
__device__ float g_Z[Bn * SEG];                // per-segment exp-sum at local max
__device__ float g_gm[Bn];                     // global max per batch
__device__ float g_invZ[Bn];                   // 1/Z per batch

// ---------------------------------------------------------------------------
// K1: w[c] = sum_u W1[c,u] * V[u]   (one warp per output c)
// ---------------------------------------------------------------------------
__global__ void k_w(const float* __restrict__ W1, const float* __restrict__ V) {
    int warp = (blockIdx.x * blockDim.x + threadIdx.x) >> 5;
    int lane = threadIdx.x & 31;
    if (warp >= CONCATn) return;
    const float4* row = reinterpret_cast<const float4*>(W1 + (size_t)warp * UNITSn);
    const float4* v4  = reinterpret_cast<const float4*>(V);
    float acc = 0.f;
#pragma unroll
    for (int i = 0; i < UNITSn / 128; i++) {
        float4 a = row[lane + i * 32];
        float4 b = v4[lane + i * 32];
        acc += a.x * b.x + a.y * b.y + a.z * b.z + a.w * b.w;
    }
#pragma unroll
    for (int o = 16; o; o >>= 1) acc += __shfl_xor_sync(0xffffffffu, acc, o);
    if (lane == 0) g_w[warp] = acc;
}

// ---------------------------------------------------------------------------
// K2: qb[b] = query[b]·w[HALF:] + b1·V + bV   (one warp per batch)
// ---------------------------------------------------------------------------
__global__ void k_qb(const float* __restrict__ query, const float* __restrict__ b1,
                     const float* __restrict__ V, const float* __restrict__ bV) {
    int b = threadIdx.x >> 5;
    int lane = threadIdx.x & 31;
    const float4* q4 = reinterpret_cast<const float4*>(query + (size_t)b * DQn);
    const float4* w4 = reinterpret_cast<const float4*>(g_w + HALFn);
    const float4* b4 = reinterpret_cast<const float4*>(b1);
    const float4* v4 = reinterpret_cast<const float4*>(V);
    float acc = 0.f;
#pragma unroll
    for (int i = 0; i < DQn / 128; i++) {
        float4 q = q4[lane + i * 32];
        float4 w = w4[lane + i * 32];
        acc += q.x * w.x + q.y * w.y + q.z * w.z + q.w * w.w;
        float4 bb = b4[lane + i * 32];
        float4 vv = v4[lane + i * 32];
        acc += bb.x * vv.x + bb.y * vv.y + bb.z * vv.z + bb.w * vv.w;
    }
#pragma unroll
    for (int o = 16; o; o >>= 1) acc += __shfl_xor_sync(0xffffffffu, acc, o);
    if (lane == 0) g_qb[b] = acc + bV[0];
}

// ---------------------------------------------------------------------------
// K3 (kS): per (seg,b) block — scores + online softmax + FIRST-HALF context.
//   Reads only values[:,:, :1024] (256 MB). Phase-B re-reads hit L1/L2.
//   2 __syncthreads per 16-row tile.
// ---------------------------------------------------------------------------
__global__ __launch_bounds__(512) void kS(const float* __restrict__ values) {
    __shared__ float sw[HALFn];     // 4 KB
    __shared__ float s_s[TILE];
    __shared__ float s_e[TILE];

    int seg = blockIdx.x, b = blockIdx.y;
    int tid = threadIdx.x, warp = tid >> 5, lane = tid & 31;

    for (int i = tid; i < HALFn; i += 512) sw[i] = g_w[i];
    float qb = g_qb[b];
    __syncthreads();

    int tbase = seg * TS;
    const float* base = values + ((size_t)(b * Tn + tbase)) * Fn;
    const float4* w4 = reinterpret_cast<const float4*>(sw);

    float2 acc = make_float2(0.f, 0.f);   // thread owns first-half cols [2*tid, 2*tid+1]
    float m_run = -1e30f;
    float Z = 0.f;

#pragma unroll 1
    for (int tile = 0; tile < TS / TILE; tile++) {
        // ---- phase A: scores (warp per row, first half only) ----
        const float4* row4 = reinterpret_cast<const float4*>(
            base + (size_t)(tile * TILE + warp) * Fn);
        float d = 0.f;
#pragma unroll
        for (int i = 0; i < HALFn / 128; i++) {
            float4 v = row4[lane + i * 32];
            float4 w = w4[lane + i * 32];
            d += v.x * w.x + v.y * w.y + v.z * w.z + v.w * w.w;
        }
#pragma unroll
        for (int o = 16; o; o >>= 1) d += __shfl_xor_sync(0xffffffffu, d, o);
        if (lane == 0) {
            float s = d + qb;
            s_s[warp] = s;
            g_score[b * Tn + tbase + tile * TILE + warp] = s;
        }
        __syncthreads();

        // ---- online softmax bookkeeping ----
        float tm = s_s[0];
#pragma unroll
        for (int i = 1; i < TILE; i++) tm = fmaxf(tm, s_s[i]);
        float new_m = fmaxf(m_run, tm);
        if (warp == 0 && lane < TILE) s_e[lane] = __expf(s_s[lane] - new_m);
        float corr = __expf(m_run - new_m);
        m_run = new_m;
        __syncthreads();

        float esum = 0.f;
#pragma unroll
        for (int i = 0; i < TILE; i++) esum += s_e[i];
        Z = Z * corr + esum;
        acc.x *= corr; acc.y *= corr;

        // ---- phase B: weighted accumulate of first half (L1/L2 hits) ----
        const float2* vp = reinterpret_cast<const float2*>(
            base + (size_t)(tile * TILE) * Fn) + tid;
#pragma unroll
        for (int t = 0; t < TILE; t++) {
            float e = s_e[t];
            float2 v = vp[(size_t)t * (Fn / 2)];
            acc.x += e * v.x;
            acc.y += e * v.y;
        }
        // no sync needed: s_s reads were pre-sync2; s_e reads ordered by next sync1
    }

    reinterpret_cast<float2*>(g_partialA + ((size_t)(b * SEG + seg)) * HALFn)[tid] = acc;
    if (tid == 0) {
        g_m[b * SEG + seg] = m_run;
        g_Z[b * SEG + seg] = Z;
    }
}

// ---------------------------------------------------------------------------
// K4: per-batch global max + 1/Z
// ---------------------------------------------------------------------------
__global__ void k_stats() {
    int b = threadIdx.x;
    if (b >= Bn) return;
    float gm = -1e30f;
#pragma unroll
    for (int s = 0; s < SEG; s++) gm = fmaxf(gm, g_m[b * SEG + s]);
    float Zg = 0.f;
#pragma unroll
    for (int s = 0; s < SEG; s++) Zg += g_Z[b * SEG + s] * __expf(g_m[b * SEG + s] - gm);
    g_gm[b] = gm;
    g_invZ[b] = 1.0f / Zg;
}

// ---------------------------------------------------------------------------
// K5 (kC2): SECOND-HALF context, pure barrier-free stream (256 MB).
//   Also writes the normalized attention weights to d_out.
// ---------------------------------------------------------------------------
__global__ __launch_bounds__(256) void kC2(const float* __restrict__ values,
                                           float* __restrict__ aw) {
    __shared__ float sa[TS];
    int seg = blockIdx.x, b = blockIdx.y;
    int tid = threadIdx.x;
    int tbase = seg * TS;

    float gm = g_gm[b], inv = g_invZ[b];
    if (tid < TS) {
        float w = __expf(g_score[b * Tn + tbase + tid] - gm) * inv;
        sa[tid] = w;
        aw[b * Tn + tbase + tid] = w;
    }
    __syncthreads();

    // thread owns second-half float4 col group tid (256*4 = 1024 cols)
    const float4* vp = reinterpret_cast<const float4*>(
        values + ((size_t)(b * Tn + tbase)) * Fn + HALFn) + tid;
    float4 acc = make_float4(0.f, 0.f, 0.f, 0.f);
#pragma unroll 8
    for (int t = 0; t < TS; t++) {
        float a = sa[t];
        float4 v = vp[(size_t)t * (Fn / 4)];
        acc.x += a * v.x;
        acc.y += a * v.y;
        acc.z += a * v.z;
        acc.w += a * v.w;
    }
    reinterpret_cast<float4*>(g_partialB + ((size_t)(b * SEG + seg)) * HALFn)[tid] = acc;
}

// ---------------------------------------------------------------------------
// K6: combine partials -> context[b, 0..2047]
//   first half:  sum_s partialA[s] * e^{m_s-gm} / Z
//   second half: sum_s partialB[s]   (already final-weighted)
// ---------------------------------------------------------------------------
__global__ __launch_bounds__(512) void k_comb(float* __restrict__ ctx) {
    int b = blockIdx.x;
    int tid = threadIdx.x;
    __shared__ float swt[SEG];
    if (tid < SEG) swt[tid] = __expf(g_m[b * SEG + tid] - g_gm[b]) * g_invZ[b];
    __syncthreads();

    if (tid < 256) {
        float4 a = make_float4(0.f, 0.f, 0.f, 0.f);
#pragma unroll
        for (int s = 0; s < SEG; s++) {
            float w = swt[s];
            float4 c = reinterpret_cast<const float4*>(
                g_partialA + ((size_t)(b * SEG + s)) * HALFn)[tid];
            a.x += w * c.x; a.y += w * c.y; a.z += w * c.z; a.w += w * c.w;
        }
        reinterpret_cast<float4*>(ctx + (size_t)b * Fn)[tid] = a;
    } else {
        int t2 = tid - 256;
        float4 a = make_float4(0.f, 0.f, 0.f, 0.f);
#pragma unroll
        for (int s = 0; s < SEG; s++) {
            float4 c = reinterpret_cast<const float4*>(
                g_partialB + ((size_t)(b * SEG + s)) * HALFn)[t2];
            a.x += c.x; a.y += c.y; a.z += c.z; a.w += c.w;
        }
        reinterpret_cast<float4*>(ctx + (size_t)b * Fn + HALFn)[t2] = a;
    }
}

// ---------------------------------------------------------------------------
extern "C" void kernel_launch(void* const* d_in, const int* in_sizes, int n_in,
                              void* d_out, int out_size) {
    const float* query  = (const float*)d_in[0];
    const float* values = (const float*)d_in[1];
    const float* W1     = (const float*)d_in[2];
    const float* b1     = (const float*)d_in[3];
    const float* V      = (const float*)d_in[4];
    const float* bV     = (const float*)d_in[5];

    float* out = (float*)d_out;
    float* ctx = out;                 // [B, F]   context_vector (32,1,2048)
    float* aw  = out + Bn * Fn;       // [B, T]   attention_weights (32,2048,1)

    k_w<<<CONCATn / 8, 256>>>(W1, V);
    k_qb<<<1, 1024>>>(query, b1, V, bV);
    dim3 g(SEG, Bn);
    kS<<<g, 512>>>(values);
    k_stats<<<1, 32>>>();
    kC2<<<g, 256>>>(values, aw);
    k_comb<<<Bn, 512>>>(ctx);
}